// round 11
// baseline (speedup 1.0000x reference)
#include <cuda_runtime.h>
#include <cuda_bf16.h>
#include <stdint.h>
#include <math.h>

// Problem constants
#define HDIM   2048
#define NACT   64
#define NSTEPS 32
#define NGATE  (4 * HDIM)          // 8192 gate rows per layer

#define L_THREADS 64               // threads per block in layer kernels (2 warps)
#define L_WARPS   (L_THREADS / 32)
#define L_GRID    (NGATE / 4 / L_WARPS)   // 2048 warps total -> 1024 blocks

#define CONV_BLOCKS 4096           // prologue: blocks doing bf16 conversion
#define GX_BLOCKS   256            // prologue: blocks doing gx precompute

// Programmatic dependent launch: overlap each kernel's recurrent-weight
// streaming with its predecessor's tail. Set to 0 to revert to plain
// serialized launches (bit-identical results).
#define USE_PDL 1

// JAX threefry RNG scheme selector (flip if actions mismatch):
//  0: legacy split (pair counters) + legacy pair-layout bits
//  1: partitionable split (foldlike) + bits[i] = o0 ^ o1   <- default (matches jax prng.py)
//  2: partitionable split + bits[i] = o1
//  3: partitionable split + bits[i] = o0
#define RNG_SCHEME 1

// ---------------------------------------------------------------------------
// Persistent device state (no allocations allowed -> __device__ globals)
// ---------------------------------------------------------------------------
__device__ float g_h[2][2][HDIM];                 // [layer][pingpong][H]
__device__ float g_c[2][HDIM];                    // [layer][H]
__device__ int   g_action;
__device__ float g_logp;
__device__ unsigned int g_done_ctr;               // last-block-done counter

// bf16 weight cache, rebuilt every replay. wih only needed for layer 1.
__device__ __nv_bfloat16 g_wih1_b[4 * HDIM * HDIM];
__device__ __nv_bfloat16 g_whh_b[2][4 * HDIM * HDIM];
__device__ float         g_bias [2][4 * HDIM];    // bih + bhh folded

// Precomputed layer-0 input gates: gx[input][gate_row],
// input 0..63 = action_emb rows, input 64 = start_token. fp32, 2.1 MB.
__device__ float g_gx[65][NGATE];

__device__ __forceinline__ float warp_sum(float v) {
    #pragma unroll
    for (int o = 16; o; o >>= 1) v += __shfl_down_sync(0xffffffffu, v, o);
    return v;
}

// PDL device controls. Both are no-ops when the kernel was launched without
// the programmatic-serialization attribute (t=0 kernels, prologue).
__device__ __forceinline__ void pdl_wait() {
    asm volatile("griddepcontrol.wait;" ::: "memory");
}
__device__ __forceinline__ void pdl_trigger() {
    asm volatile("griddepcontrol.launch_dependents;" ::: "memory");
}

// ---------------------------------------------------------------------------
// Prologue part A (blocks 0..CONV_BLOCKS-1): fp32 -> bf16 weight conversion
// (whh both layers, wih layer 1 only), bias fold, state init.
// ---------------------------------------------------------------------------
__device__ void prologue_convert(int cb,
                                 const float* __restrict__ wih,
                                 const float* __restrict__ whh,
                                 const float* __restrict__ bih,
                                 const float* __restrict__ bhh)
{
    const size_t nh4 = (size_t)2 * NGATE * HDIM / 4;     // whh float4 count (both layers)
    const size_t ni4 = (size_t)NGATE * HDIM / 4;         // wih layer-1 float4 count
    const float4* wh4 = (const float4*)whh;
    const float4* wi4 = (const float4*)(wih + (size_t)NGATE * HDIM);  // layer 1
    __nv_bfloat162* oh = (__nv_bfloat162*)g_whh_b;
    __nv_bfloat162* oi = (__nv_bfloat162*)g_wih1_b;

    size_t stride = (size_t)CONV_BLOCKS * blockDim.x;
    size_t t0 = cb * (size_t)blockDim.x + threadIdx.x;
    for (size_t i = t0; i < nh4; i += stride) {
        float4 b = __ldcs(&wh4[i]);
        oh[2 * i]     = __floats2bfloat162_rn(b.x, b.y);
        oh[2 * i + 1] = __floats2bfloat162_rn(b.z, b.w);
    }
    for (size_t i = t0; i < ni4; i += stride) {
        float4 a = __ldcs(&wi4[i]);
        oi[2 * i]     = __floats2bfloat162_rn(a.x, a.y);
        oi[2 * i + 1] = __floats2bfloat162_rn(a.z, a.w);
    }
    int j = cb * blockDim.x + threadIdx.x;
    if (j < 2 * NGATE) {
        ((float*)g_bias)[j] = bih[j] + bhh[j];
    }
    if (j < HDIM) {           // fused init
        g_h[0][0][j] = 0.f; g_h[0][1][j] = 0.f;
        g_h[1][0][j] = 0.f; g_h[1][1][j] = 0.f;
        g_c[0][j]    = 0.f; g_c[1][j]    = 0.f;
    }
    if (j == 0) { g_action = 0; g_logp = 0.f; g_done_ctr = 0u; }
}

// ---------------------------------------------------------------------------
// Prologue part B (blocks CONV_BLOCKS..): g_gx[input][row] = (W_ih0 @ x)[row].
// 2048 warps, warp handles 4 consecutive gate rows; 16-action register chunks.
// ---------------------------------------------------------------------------
__device__ void prologue_gx(int gb,
                            const float* __restrict__ wih0,
                            const float* __restrict__ action_emb,
                            const float* __restrict__ start_token)
{
    int warp_id = gb * (int)(blockDim.x >> 5) + (int)(threadIdx.x >> 5); // 0..2047
    int lane    = threadIdx.x & 31;
    int r0      = warp_id * 4;                                           // rows r0..r0+3

    const float4* w4[4];
    #pragma unroll
    for (int j = 0; j < 4; j++)
        w4[j] = (const float4*)(wih0 + (size_t)(r0 + j) * HDIM);
    const float4* e4 = (const float4*)action_emb;   // [NACT * 512] float4
    const float4* s4 = (const float4*)start_token;  // [512] float4

    #pragma unroll 1
    for (int c = 0; c < 4; c++) {                   // 4 chunks of 16 actions
        float acc[4][16];
        #pragma unroll
        for (int j = 0; j < 4; j++)
            #pragma unroll
            for (int a = 0; a < 16; a++) acc[j][a] = 0.f;

        for (int kt = 0; kt < 16; kt++) {
            int k = lane + kt * 32;                 // float4 index, 512 per row
            float4 wv[4];
            #pragma unroll
            for (int j = 0; j < 4; j++) wv[j] = w4[j][k];
            #pragma unroll
            for (int a = 0; a < 16; a++) {
                float4 e = e4[(size_t)(c * 16 + a) * 512 + k];
                #pragma unroll
                for (int j = 0; j < 4; j++)
                    acc[j][a] += wv[j].x*e.x + wv[j].y*e.y + wv[j].z*e.z + wv[j].w*e.w;
            }
        }
        #pragma unroll
        for (int j = 0; j < 4; j++)
            #pragma unroll
            for (int a = 0; a < 16; a++) {
                float v = warp_sum(acc[j][a]);
                if (lane == 0) g_gx[c * 16 + a][r0 + j] = v;
            }
    }

    {   // start token (input index 64)
        float acc[4] = {0.f, 0.f, 0.f, 0.f};
        for (int kt = 0; kt < 16; kt++) {
            int k = lane + kt * 32;
            float4 e = s4[k];
            #pragma unroll
            for (int j = 0; j < 4; j++) {
                float4 wv = w4[j][k];
                acc[j] += wv.x*e.x + wv.y*e.y + wv.z*e.z + wv.w*e.w;
            }
        }
        #pragma unroll
        for (int j = 0; j < 4; j++) {
            float v = warp_sum(acc[j]);
            if (lane == 0) g_gx[64][r0 + j] = v;
        }
    }
}

// Merged prologue: memory-bound conversion co-scheduled with FLOP-bound gx.
__global__ void __launch_bounds__(256) prologue_kernel(
    const float* __restrict__ wih, const float* __restrict__ whh,
    const float* __restrict__ bih, const float* __restrict__ bhh,
    const float* __restrict__ action_emb, const float* __restrict__ start_token)
{
    if (blockIdx.x < CONV_BLOCKS)
        prologue_convert(blockIdx.x, wih, whh, bih, bhh);
    else
        prologue_gx(blockIdx.x - CONV_BLOCKS, wih, action_emb, start_token);
}

// dot of 8 bf16 weights (packed in uint4) with 8 fp32 activations (two float4)
__device__ __forceinline__ float dot8(uint4 w, float4 a, float4 b) {
    float2 f0 = __bfloat1622float2(*(__nv_bfloat162*)&w.x);
    float2 f1 = __bfloat1622float2(*(__nv_bfloat162*)&w.y);
    float2 f2 = __bfloat1622float2(*(__nv_bfloat162*)&w.z);
    float2 f3 = __bfloat1622float2(*(__nv_bfloat162*)&w.w);
    return f0.x*a.x + f0.y*a.y + f1.x*a.z + f1.y*a.w
         + f2.x*b.x + f2.y*b.y + f3.x*b.z + f3.y*b.w;
}

__device__ __forceinline__ void lstm_pointwise(float a0, float a1, float a2, float a3,
                                               const float* bs, int w,
                                               float* cst, float* h_out) {
    float gi = a0 + bs[w           ];
    float gf = a1 + bs[w +     HDIM];
    float gg = a2 + bs[w + 2 * HDIM];
    float go = a3 + bs[w + 3 * HDIM];
    float si = 1.f / (1.f + expf(-gi));
    float sf = 1.f / (1.f + expf(-gf));
    float tg = tanhf(gg);
    float so = 1.f / (1.f + expf(-go));
    float cn = sf * cst[w] + si * tg;
    cst[w]   = cn;
    h_out[w] = so * tanhf(cn);
}

// ---------------------------------------------------------------------------
// Layer 0. PRE-SYNC: W_hh0 @ h0(t-1) dots (depends only on state from two
// kernels back). POST-SYNC: read g_action (head of t-1), add gx, pointwise.
// ---------------------------------------------------------------------------
__global__ void __launch_bounds__(L_THREADS) lstm_layer0_kernel(int parity, int step)
{
    const float* h_in  = g_h[0][parity];
    float*       h_out = g_h[0][parity ^ 1];
    float*       cst   = g_c[0];

    int w    = blockIdx.x * L_WARPS + (threadIdx.x >> 5);  // 0..2047
    int lane = threadIdx.x & 31;

    const float4* h4 = (const float4*)h_in;
    const uint4* wh0 = (const uint4*)(g_whh_b[0] + (size_t)(w           ) * HDIM);
    const uint4* wh1 = (const uint4*)(g_whh_b[0] + (size_t)(w +     HDIM) * HDIM);
    const uint4* wh2 = (const uint4*)(g_whh_b[0] + (size_t)(w + 2 * HDIM) * HDIM);
    const uint4* wh3 = (const uint4*)(g_whh_b[0] + (size_t)(w + 3 * HDIM) * HDIM);

    float a0 = 0.f, a1 = 0.f, a2 = 0.f, a3 = 0.f;
    #pragma unroll
    for (int it = 0; it < 8; it++) {
        int k = lane + it * 32;                // uint4 index: 256 per row
        float4 ha = h4[2 * k], hb = h4[2 * k + 1];
        a0 += dot8(__ldcs(&wh0[k]), ha, hb);
        a1 += dot8(__ldcs(&wh1[k]), ha, hb);
        a2 += dot8(__ldcs(&wh2[k]), ha, hb);
        a3 += dot8(__ldcs(&wh3[k]), ha, hb);
    }
    a0 = warp_sum(a0); a1 = warp_sum(a1); a2 = warp_sum(a2); a3 = warp_sum(a3);

    pdl_wait();       // predecessor (layer1+head of t-1) now fully visible
    pdl_trigger();    // release successor (its pre-sync depends on t-1 state)

    if (lane == 0) {
        int idx = (step == 0) ? 64 : g_action;   // input selector into g_gx
        const float* gx = g_gx[idx];
        a0 += gx[w           ];
        a1 += gx[w +     HDIM];
        a2 += gx[w + 2 * HDIM];
        a3 += gx[w + 3 * HDIM];
        lstm_pointwise(a0, a1, a2, a3, g_bias[0], w, cst, h_out);
    }
}

// ---------------------------------------------------------------------------
// Threefry2x32 (20 rounds) — bit-exact vs JAX
// ---------------------------------------------------------------------------
__device__ __forceinline__ void threefry2x32(uint32_t k0, uint32_t k1,
                                             uint32_t x0, uint32_t x1,
                                             uint32_t* o0, uint32_t* o1)
{
    uint32_t ks2 = k0 ^ k1 ^ 0x1BD11BDAu;
    x0 += k0; x1 += k1;
    #define TF_RND(r) { x0 += x1; x1 = (x1 << (r)) | (x1 >> (32 - (r))); x1 ^= x0; }
    TF_RND(13) TF_RND(15) TF_RND(26) TF_RND(6)   x0 += k1;  x1 += ks2 + 1u;
    TF_RND(17) TF_RND(29) TF_RND(16) TF_RND(24)  x0 += ks2; x1 += k0  + 2u;
    TF_RND(13) TF_RND(15) TF_RND(26) TF_RND(6)   x0 += k0;  x1 += k1  + 3u;
    TF_RND(17) TF_RND(29) TF_RND(16) TF_RND(24)  x0 += k1;  x1 += ks2 + 4u;
    TF_RND(13) TF_RND(15) TF_RND(26) TF_RND(6)   x0 += ks2; x1 += k0  + 5u;
    #undef TF_RND
    *o0 = x0; *o1 = x1;
}

// per-step key k_t = split(key(42), NSTEPS)[step]
__device__ __forceinline__ void step_key(int step, uint32_t* k0, uint32_t* k1) {
#if RNG_SCHEME == 0
    uint32_t o0, o1;
    int idx0 = 2 * step, idx1 = 2 * step + 1;
    uint32_t blk0 = (idx0 < 32) ? (uint32_t)idx0 : (uint32_t)(idx0 - 32);
    threefry2x32(0u, 42u, blk0, blk0 + 32u, &o0, &o1);
    *k0 = (idx0 < 32) ? o0 : o1;
    uint32_t blk1 = (idx1 < 32) ? (uint32_t)idx1 : (uint32_t)(idx1 - 32);
    threefry2x32(0u, 42u, blk1, blk1 + 32u, &o0, &o1);
    *k1 = (idx1 < 32) ? o0 : o1;
#else
    threefry2x32(0u, 42u, 0u, (uint32_t)step, k0, k1);   // foldlike split
#endif
}

// random bits for element `lane` and `lane+32` of a 64-element draw
__device__ __forceinline__ void draw_bits(uint32_t k0, uint32_t k1, int lane,
                                          uint32_t* ba, uint32_t* bb) {
#if RNG_SCHEME == 0
    uint32_t r0, r1;
    threefry2x32(k0, k1, (uint32_t)lane, (uint32_t)(lane + 32), &r0, &r1);
    *ba = r0; *bb = r1;
#elif RNG_SCHEME == 1
    uint32_t r0, r1;
    threefry2x32(k0, k1, 0u, (uint32_t)lane,        &r0, &r1); *ba = r0 ^ r1;
    threefry2x32(k0, k1, 0u, (uint32_t)(lane + 32), &r0, &r1); *bb = r0 ^ r1;
#elif RNG_SCHEME == 2
    uint32_t r0, r1;
    threefry2x32(k0, k1, 0u, (uint32_t)lane,        &r0, &r1); *ba = r1;
    threefry2x32(k0, k1, 0u, (uint32_t)(lane + 32), &r0, &r1); *bb = r1;
#else
    uint32_t r0, r1;
    threefry2x32(k0, k1, 0u, (uint32_t)lane,        &r0, &r1); *ba = r0;
    threefry2x32(k0, k1, 0u, (uint32_t)(lane + 32), &r0, &r1); *bb = r0;
#endif
}

// ---------------------------------------------------------------------------
// Layer 1 + fused head. PRE-SYNC: W_hh1 @ h1(t-1) dots, staging of 3 of 4
// W_ih1 gate rows into smem, and L2 prefetch of this step's head weights
// (all independent of t-state). POST-SYNC: input-half dots from smem (gate 3
// from global), pointwise, last-block head (L2-hot, 32 rows/warp) + sampling.
// ---------------------------------------------------------------------------
__global__ void __launch_bounds__(L_THREADS) lstm_layer1_head_kernel(
    const float* __restrict__ hw,   // [NACT, HDIM] head weights for this step
    const float* __restrict__ hb,   // [NACT]
    float* __restrict__ out, int step, int parity, int write_logp)
{
    // 2 warps x 3 gates x 256 uint4 = 24 KB (occupancy-safe: 9 blocks/SM)
    __shared__ uint4 s_wi[L_WARPS][3][256];

    const float* h_in  = g_h[1][parity];
    float*       h_out = g_h[1][parity ^ 1];
    float*       cst   = g_c[1];

    int w    = blockIdx.x * L_WARPS + (threadIdx.x >> 5);
    int wp   = threadIdx.x >> 5;
    int lane = threadIdx.x & 31;

    // L2-prefetch this block's 4 x 128B slice of head_w (512 KB over 1024
    // blocks) so the last block's head reads hit L2 instead of DRAM.
    if (threadIdx.x < 4) {
        const char* p = (const char*)hw
                      + ((size_t)blockIdx.x * 4 + threadIdx.x) * 128;
        asm volatile("prefetch.global.L2 [%0];" :: "l"(p));
    }

    const uint4* wi0 = (const uint4*)(g_wih1_b + (size_t)(w           ) * HDIM);
    const uint4* wi1 = (const uint4*)(g_wih1_b + (size_t)(w +     HDIM) * HDIM);
    const uint4* wi2 = (const uint4*)(g_wih1_b + (size_t)(w + 2 * HDIM) * HDIM);
    const uint4* wi3 = (const uint4*)(g_wih1_b + (size_t)(w + 3 * HDIM) * HDIM);
    const uint4* wh0 = (const uint4*)(g_whh_b[1] + (size_t)(w           ) * HDIM);
    const uint4* wh1 = (const uint4*)(g_whh_b[1] + (size_t)(w +     HDIM) * HDIM);
    const uint4* wh2 = (const uint4*)(g_whh_b[1] + (size_t)(w + 2 * HDIM) * HDIM);
    const uint4* wh3 = (const uint4*)(g_whh_b[1] + (size_t)(w + 3 * HDIM) * HDIM);

    float a0 = 0.f, a1 = 0.f, a2 = 0.f, a3 = 0.f;

    {   // PRE-SYNC: recurrent half + W_ih1 staging (both independent of t-state)
        const float4* h4 = (const float4*)h_in;
        #pragma unroll
        for (int it = 0; it < 8; it++) {
            int k = lane + it * 32;
            s_wi[wp][0][k] = __ldcs(&wi0[k]);
            s_wi[wp][1][k] = __ldcs(&wi1[k]);
            s_wi[wp][2][k] = __ldcs(&wi2[k]);
            float4 ha = h4[2 * k], hb2 = h4[2 * k + 1];
            a0 += dot8(__ldcs(&wh0[k]), ha, hb2);
            a1 += dot8(__ldcs(&wh1[k]), ha, hb2);
            a2 += dot8(__ldcs(&wh2[k]), ha, hb2);
            a3 += dot8(__ldcs(&wh3[k]), ha, hb2);
        }
    }

    pdl_wait();       // layer0(t) writes to g_h[0][parity^1] now visible
    pdl_trigger();    // release layer0(t+1) (its pre-sync needs t-1 state only)

    {   // POST-SYNC: input half (x = fresh h0); gates 0-2 from smem, gate 3 global
        const float4* x4 = (const float4*)g_h[0][parity ^ 1];
        #pragma unroll
        for (int it = 0; it < 8; it++) {
            int k = lane + it * 32;
            float4 xa = x4[2 * k], xb = x4[2 * k + 1];
            a0 += dot8(s_wi[wp][0][k], xa, xb);
            a1 += dot8(s_wi[wp][1][k], xa, xb);
            a2 += dot8(s_wi[wp][2][k], xa, xb);
            a3 += dot8(__ldcs(&wi3[k]), xa, xb);
        }
    }
    a0 = warp_sum(a0); a1 = warp_sum(a1); a2 = warp_sum(a2); a3 = warp_sum(a3);

    if (lane == 0)
        lstm_pointwise(a0, a1, a2, a3, g_bias[1], w, cst, h_out);

    // ---- last-block detection ----
    __shared__ bool s_is_last;
    __syncthreads();
    if (threadIdx.x == 0) {
        __threadfence();                               // publish h_out writes
        unsigned v = atomicAdd(&g_done_ctr, 1u);
        s_is_last = (v == gridDim.x - 1);
    }
    __syncthreads();
    if (!s_is_last) return;                            // block-uniform branch
    __threadfence();                                   // see all blocks' h_out
    if (threadIdx.x == 0) g_done_ctr = 0u;             // reset for next launch

    // ---- head: 2 warps x 32 rows in ONE pass (32 loads in flight per warp,
    //      L2-hot from the prefetch) ----
    __shared__ float s_logits[NACT];
    const float4* h4 = (const float4*)h_out;
    const int ROWS_PER_WARP = NACT / L_WARPS;          // 32

    {
        int rbase = wp * ROWS_PER_WARP;
        float acc[ROWS_PER_WARP];
        #pragma unroll
        for (int r = 0; r < ROWS_PER_WARP; r++) acc[r] = 0.f;
        const float4* wbase = (const float4*)hw + (size_t)rbase * 512;
        #pragma unroll 2
        for (int it = 0; it < 16; it++) {
            int k = lane + it * 32;
            float4 hv = h4[k];
            #pragma unroll
            for (int r = 0; r < ROWS_PER_WARP; r++) {
                float4 a = wbase[(size_t)r * 512 + k];
                acc[r] += a.x*hv.x + a.y*hv.y + a.z*hv.z + a.w*hv.w;
            }
        }
        #pragma unroll
        for (int r = 0; r < ROWS_PER_WARP; r++) {
            float v = warp_sum(acc[r]);
            if (lane == 0) s_logits[rbase + r] = v + hb[rbase + r];
        }
    }
    __syncthreads();

    if (wp == 0) {
        uint32_t k0, k1;
        step_key(step, &k0, &k1);
        uint32_t bits_a, bits_b;
        draw_bits(k0, k1, lane, &bits_a, &bits_b);

        // jax uniform(minval=tiny,maxval=1): f = bitcast(bits>>9 | 1.0f)-1;
        // u = max(tiny, f*(1-tiny)+tiny)
        const float TINY = 1.1754943508222875e-38f;
        float ua = __uint_as_float((bits_a >> 9) | 0x3f800000u) - 1.0f;
        float ub = __uint_as_float((bits_b >> 9) | 0x3f800000u) - 1.0f;
        ua = fmaxf(ua * (1.0f - TINY) + TINY, TINY);
        ub = fmaxf(ub * (1.0f - TINY) + TINY, TINY);
        float ga = -logf(-logf(ua));
        float gb = -logf(-logf(ub));

        float l0 = s_logits[lane], l1 = s_logits[lane + 32];
        float v0 = l0 + ga, v1 = l1 + gb;

        // argmax, first-index tie-break (matches jnp.argmax)
        float bv; int bi;
        if (v1 > v0) { bv = v1; bi = lane + 32; } else { bv = v0; bi = lane; }
        #pragma unroll
        for (int o = 16; o; o >>= 1) {
            float ov = __shfl_xor_sync(0xffffffffu, bv, o);
            int   oi = __shfl_xor_sync(0xffffffffu, bi, o);
            if (ov > bv || (ov == bv && oi < bi)) { bv = ov; bi = oi; }
        }
        // logsumexp over all 64 logits
        float m = fmaxf(l0, l1);
        #pragma unroll
        for (int o = 16; o; o >>= 1) m = fmaxf(m, __shfl_xor_sync(0xffffffffu, m, o));
        float s = expf(l0 - m) + expf(l1 - m);
        #pragma unroll
        for (int o = 16; o; o >>= 1) s += __shfl_xor_sync(0xffffffffu, s, o);

        if (lane == 0) {
            float logp = s_logits[bi] - (logf(s) + m);
            g_action = bi;
            float tot = g_logp + logp;
            g_logp = tot;
            out[step] = (float)bi;                                    // actions
            if (write_logp && step == NSTEPS - 1) out[NSTEPS] = tot;  // sum(logps)
        }
    }
}

// ---------------------------------------------------------------------------
// PDL-aware launch helpers (stream 0 == legacy default, same as <<< >>>)
// ---------------------------------------------------------------------------
static void launch_layer0(int parity, int step, int pdl) {
    cudaLaunchConfig_t cfg = {};
    cfg.gridDim  = dim3(L_GRID);
    cfg.blockDim = dim3(L_THREADS);
    cfg.stream   = 0;
    cudaLaunchAttribute attr[1];
    attr[0].id = cudaLaunchAttributeProgrammaticStreamSerialization;
    attr[0].val.programmaticStreamSerializationAllowed = 1;
    cfg.attrs    = attr;
    cfg.numAttrs = pdl ? 1 : 0;
    cudaLaunchKernelEx(&cfg, lstm_layer0_kernel, parity, step);
}

static void launch_layer1(const float* hw, const float* hb, float* out,
                          int step, int parity, int write_logp, int pdl) {
    cudaLaunchConfig_t cfg = {};
    cfg.gridDim  = dim3(L_GRID);
    cfg.blockDim = dim3(L_THREADS);
    cfg.stream   = 0;
    cudaLaunchAttribute attr[1];
    attr[0].id = cudaLaunchAttributeProgrammaticStreamSerialization;
    attr[0].val.programmaticStreamSerializationAllowed = 1;
    cfg.attrs    = attr;
    cfg.numAttrs = pdl ? 1 : 0;
    cudaLaunchKernelEx(&cfg, lstm_layer1_head_kernel,
                       hw, hb, out, step, parity, write_logp);
}

// ---------------------------------------------------------------------------
// kernel_launch: prologue + 32 x (layer0, layer1+head)  = 65 graph nodes
// ---------------------------------------------------------------------------
extern "C" void kernel_launch(void* const* d_in, const int* in_sizes, int n_in,
                              void* d_out, int out_size)
{
    const float* start_token = (const float*)d_in[0];
    const float* action_emb  = (const float*)d_in[1];
    const float* w_ih        = (const float*)d_in[2];  // [2, 4H, H]
    const float* w_hh        = (const float*)d_in[3];  // [2, 4H, H]
    const float* b_ih        = (const float*)d_in[4];  // [2, 4H]
    const float* b_hh        = (const float*)d_in[5];  // [2, 4H]
    const float* head_w      = (const float*)d_in[6];  // [32, 64, H]
    const float* head_b      = (const float*)d_in[7];  // [32, 64]
    float* out = (float*)d_out;
    int write_logp = (out_size >= NSTEPS + 1) ? 1 : 0;

    prologue_kernel<<<CONV_BLOCKS + GX_BLOCKS, 256>>>(
        w_ih, w_hh, b_ih, b_hh, action_emb, start_token);

    for (int t = 0; t < NSTEPS; t++) {
        int p = t & 1;
        // t=0 kernels launch WITHOUT the PDL attribute: their pre-sync reads
        // prologue outputs, so they must fully wait for the prologue.
#if USE_PDL
        launch_layer0(p, t, /*pdl=*/t > 0);
        launch_layer1(head_w + (size_t)t * NACT * HDIM,
                      head_b + (size_t)t * NACT,
                      out, t, p, write_logp, /*pdl=*/1);
#else
        launch_layer0(p, t, 0);
        launch_layer1(head_w + (size_t)t * NACT * HDIM,
                      head_b + (size_t)t * NACT,
                      out, t, p, write_logp, 0);
#endif
    }
}

// round 14
// speedup vs baseline: 1.4822x; 1.4822x over previous
#include <cuda_runtime.h>
#include <cuda_bf16.h>
#include <stdint.h>
#include <math.h>

// Problem constants
#define HDIM   2048
#define NACT   64
#define NSTEPS 32
#define NGATE  (4 * HDIM)          // 8192 gate rows per layer

#define L_THREADS 128              // 4 warps per block, block = 1 hidden unit
#define L_MINBLK  8                // min blocks/SM -> caps regs at 64/thread
#define L_GRID    HDIM             // 2048 blocks

#define CONV_BLOCKS 4096           // prologue: blocks doing bf16 conversion
#define GX_BLOCKS   256            // prologue: blocks doing gx precompute

// Programmatic dependent launch (verified passing in round 11).
#define USE_PDL 1

// JAX threefry RNG scheme (scheme 1 verified bit-exact in round 11).
#define RNG_SCHEME 1

// ---------------------------------------------------------------------------
// Persistent device state (no allocations allowed -> __device__ globals)
// ---------------------------------------------------------------------------
__device__ float g_h[2][2][HDIM];                 // [layer][pingpong][H]
__device__ float g_c[2][HDIM];                    // [layer][H]
__device__ int   g_action;
__device__ float g_logp;
__device__ unsigned int g_done_ctr;               // last-block-done counter

// bf16 weight cache, rebuilt every replay. wih only needed for layer 1.
__device__ __nv_bfloat16 g_wih1_b[4 * HDIM * HDIM];
__device__ __nv_bfloat16 g_whh_b[2][4 * HDIM * HDIM];
__device__ float         g_bias [2][4 * HDIM];    // bih + bhh folded

// Precomputed layer-0 input gates: gx[input][gate_row],
// input 0..63 = action_emb rows, input 64 = start_token. fp32, 2.1 MB.
__device__ float g_gx[65][NGATE];

__device__ __forceinline__ float warp_sum(float v) {
    #pragma unroll
    for (int o = 16; o; o >>= 1) v += __shfl_down_sync(0xffffffffu, v, o);
    return v;
}

// PDL device controls (no-ops when launched without the PDL attribute).
__device__ __forceinline__ void pdl_wait() {
    asm volatile("griddepcontrol.wait;" ::: "memory");
}
__device__ __forceinline__ void pdl_trigger() {
    asm volatile("griddepcontrol.launch_dependents;" ::: "memory");
}

// ---------------------------------------------------------------------------
// Prologue part A: fp32 -> bf16 weight conversion, bias fold, state init.
// ---------------------------------------------------------------------------
__device__ void prologue_convert(int cb,
                                 const float* __restrict__ wih,
                                 const float* __restrict__ whh,
                                 const float* __restrict__ bih,
                                 const float* __restrict__ bhh)
{
    const size_t nh4 = (size_t)2 * NGATE * HDIM / 4;
    const size_t ni4 = (size_t)NGATE * HDIM / 4;
    const float4* wh4 = (const float4*)whh;
    const float4* wi4 = (const float4*)(wih + (size_t)NGATE * HDIM);  // layer 1
    __nv_bfloat162* oh = (__nv_bfloat162*)g_whh_b;
    __nv_bfloat162* oi = (__nv_bfloat162*)g_wih1_b;

    size_t stride = (size_t)CONV_BLOCKS * blockDim.x;
    size_t t0 = cb * (size_t)blockDim.x + threadIdx.x;
    for (size_t i = t0; i < nh4; i += stride) {
        float4 b = __ldcs(&wh4[i]);
        oh[2 * i]     = __floats2bfloat162_rn(b.x, b.y);
        oh[2 * i + 1] = __floats2bfloat162_rn(b.z, b.w);
    }
    for (size_t i = t0; i < ni4; i += stride) {
        float4 a = __ldcs(&wi4[i]);
        oi[2 * i]     = __floats2bfloat162_rn(a.x, a.y);
        oi[2 * i + 1] = __floats2bfloat162_rn(a.z, a.w);
    }
    int j = cb * blockDim.x + threadIdx.x;
    if (j < 2 * NGATE) {
        ((float*)g_bias)[j] = bih[j] + bhh[j];
    }
    if (j < HDIM) {           // fused init
        g_h[0][0][j] = 0.f; g_h[0][1][j] = 0.f;
        g_h[1][0][j] = 0.f; g_h[1][1][j] = 0.f;
        g_c[0][j]    = 0.f; g_c[1][j]    = 0.f;
    }
    if (j == 0) { g_action = 0; g_logp = 0.f; g_done_ctr = 0u; }
}

// ---------------------------------------------------------------------------
// Prologue part B: g_gx[input][row] = (W_ih0 @ x_input)[row].
// ---------------------------------------------------------------------------
__device__ void prologue_gx(int gb,
                            const float* __restrict__ wih0,
                            const float* __restrict__ action_emb,
                            const float* __restrict__ start_token)
{
    int warp_id = gb * (int)(blockDim.x >> 5) + (int)(threadIdx.x >> 5); // 0..2047
    int lane    = threadIdx.x & 31;
    int r0      = warp_id * 4;

    const float4* w4[4];
    #pragma unroll
    for (int j = 0; j < 4; j++)
        w4[j] = (const float4*)(wih0 + (size_t)(r0 + j) * HDIM);
    const float4* e4 = (const float4*)action_emb;
    const float4* s4 = (const float4*)start_token;

    #pragma unroll 1
    for (int c = 0; c < 4; c++) {
        float acc[4][16];
        #pragma unroll
        for (int j = 0; j < 4; j++)
            #pragma unroll
            for (int a = 0; a < 16; a++) acc[j][a] = 0.f;

        for (int kt = 0; kt < 16; kt++) {
            int k = lane + kt * 32;
            float4 wv[4];
            #pragma unroll
            for (int j = 0; j < 4; j++) wv[j] = w4[j][k];
            #pragma unroll
            for (int a = 0; a < 16; a++) {
                float4 e = e4[(size_t)(c * 16 + a) * 512 + k];
                #pragma unroll
                for (int j = 0; j < 4; j++)
                    acc[j][a] += wv[j].x*e.x + wv[j].y*e.y + wv[j].z*e.z + wv[j].w*e.w;
            }
        }
        #pragma unroll
        for (int j = 0; j < 4; j++)
            #pragma unroll
            for (int a = 0; a < 16; a++) {
                float v = warp_sum(acc[j][a]);
                if (lane == 0) g_gx[c * 16 + a][r0 + j] = v;
            }
    }

    {   // start token (input index 64)
        float acc[4] = {0.f, 0.f, 0.f, 0.f};
        for (int kt = 0; kt < 16; kt++) {
            int k = lane + kt * 32;
            float4 e = s4[k];
            #pragma unroll
            for (int j = 0; j < 4; j++) {
                float4 wv = w4[j][k];
                acc[j] += wv.x*e.x + wv.y*e.y + wv.z*e.z + wv.w*e.w;
            }
        }
        #pragma unroll
        for (int j = 0; j < 4; j++) {
            float v = warp_sum(acc[j]);
            if (lane == 0) g_gx[64][r0 + j] = v;
        }
    }
}

__global__ void __launch_bounds__(256) prologue_kernel(
    const float* __restrict__ wih, const float* __restrict__ whh,
    const float* __restrict__ bih, const float* __restrict__ bhh,
    const float* __restrict__ action_emb, const float* __restrict__ start_token)
{
    if (blockIdx.x < CONV_BLOCKS)
        prologue_convert(blockIdx.x, wih, whh, bih, bhh);
    else
        prologue_gx(blockIdx.x - CONV_BLOCKS, wih, action_emb, start_token);
}

// dot of 8 bf16 weights (packed in uint4) with 8 fp32 activations (two float4)
__device__ __forceinline__ float dot8(uint4 w, float4 a, float4 b) {
    float2 f0 = __bfloat1622float2(*(__nv_bfloat162*)&w.x);
    float2 f1 = __bfloat1622float2(*(__nv_bfloat162*)&w.y);
    float2 f2 = __bfloat1622float2(*(__nv_bfloat162*)&w.z);
    float2 f3 = __bfloat1622float2(*(__nv_bfloat162*)&w.w);
    return f0.x*a.x + f0.y*a.y + f1.x*a.z + f1.y*a.w
         + f2.x*b.x + f2.y*b.y + f3.x*b.z + f3.y*b.w;
}

// pointwise LSTM cell update for one hidden unit (gate pre-acts g0..g3)
__device__ __forceinline__ void lstm_pointwise4(float g0, float g1, float g2, float g3,
                                                const float* bs, int w,
                                                float* cst, float* h_out) {
    float gi = g0 + bs[w           ];
    float gf = g1 + bs[w +     HDIM];
    float gg = g2 + bs[w + 2 * HDIM];
    float go = g3 + bs[w + 3 * HDIM];
    float si = 1.f / (1.f + expf(-gi));
    float sf = 1.f / (1.f + expf(-gf));
    float tg = tanhf(gg);
    float so = 1.f / (1.f + expf(-go));
    float cn = sf * cst[w] + si * tg;
    cst[w]   = cn;
    h_out[w] = so * tanhf(cn);
}

// ---------------------------------------------------------------------------
// Layer 0. Block = 1 hidden unit; 4 warps split K into quarters.
// PRE-SYNC: W_hh0 @ h0(t-1) partial dots. POST-SYNC: g_action, gx, pointwise.
// ---------------------------------------------------------------------------
__global__ void __launch_bounds__(L_THREADS, L_MINBLK) lstm_layer0_kernel(int parity, int step)
{
    __shared__ float s_part[4][4];                 // [gate][warp]

    const float* h_in  = g_h[0][parity];
    float*       h_out = g_h[0][parity ^ 1];
    float*       cst   = g_c[0];

    int w    = blockIdx.x;                         // hidden unit 0..2047
    int wp   = threadIdx.x >> 5;
    int lane = threadIdx.x & 31;
    int k0   = wp * 64 + lane;                     // uint4 index (2 per lane)

    const float4* h4 = (const float4*)h_in;
    float4 ha0 = h4[2 * k0],        hb0 = h4[2 * k0 + 1];
    float4 ha1 = h4[2 * (k0 + 32)], hb1 = h4[2 * (k0 + 32) + 1];

    float a[4];
    #pragma unroll
    for (int g = 0; g < 4; g++) a[g] = 0.f;

    #pragma unroll
    for (int g = 0; g < 4; g++) {
        const uint4* wr = (const uint4*)(g_whh_b[0] + (size_t)(w + g * HDIM) * HDIM);
        a[g] += dot8(__ldcs(&wr[k0]),      ha0, hb0);
        a[g] += dot8(__ldcs(&wr[k0 + 32]), ha1, hb1);
    }
    #pragma unroll
    for (int g = 0; g < 4; g++) {
        float v = warp_sum(a[g]);
        if (lane == 0) s_part[g][wp] = v;
    }

    pdl_wait();       // predecessor (layer1+head of t-1) fully complete
    pdl_trigger();    // release successor (its pre-sync depends on t-1 state only)
    __syncthreads();

    if (threadIdx.x == 0) {
        int idx = (step == 0) ? 64 : g_action;
        const float* gx = g_gx[idx];
        float g0 = s_part[0][0] + s_part[0][1] + s_part[0][2] + s_part[0][3] + gx[w           ];
        float g1 = s_part[1][0] + s_part[1][1] + s_part[1][2] + s_part[1][3] + gx[w +     HDIM];
        float g2 = s_part[2][0] + s_part[2][1] + s_part[2][2] + s_part[2][3] + gx[w + 2 * HDIM];
        float g3 = s_part[3][0] + s_part[3][1] + s_part[3][2] + s_part[3][3] + gx[w + 3 * HDIM];
        lstm_pointwise4(g0, g1, g2, g3, g_bias[0], w, cst, h_out);
    }
}

// ---------------------------------------------------------------------------
// Threefry2x32 (20 rounds) — bit-exact vs JAX (verified round 11)
// ---------------------------------------------------------------------------
__device__ __forceinline__ void threefry2x32(uint32_t k0, uint32_t k1,
                                             uint32_t x0, uint32_t x1,
                                             uint32_t* o0, uint32_t* o1)
{
    uint32_t ks2 = k0 ^ k1 ^ 0x1BD11BDAu;
    x0 += k0; x1 += k1;
    #define TF_RND(r) { x0 += x1; x1 = (x1 << (r)) | (x1 >> (32 - (r))); x1 ^= x0; }
    TF_RND(13) TF_RND(15) TF_RND(26) TF_RND(6)   x0 += k1;  x1 += ks2 + 1u;
    TF_RND(17) TF_RND(29) TF_RND(16) TF_RND(24)  x0 += ks2; x1 += k0  + 2u;
    TF_RND(13) TF_RND(15) TF_RND(26) TF_RND(6)   x0 += k0;  x1 += k1  + 3u;
    TF_RND(17) TF_RND(29) TF_RND(16) TF_RND(24)  x0 += k1;  x1 += ks2 + 4u;
    TF_RND(13) TF_RND(15) TF_RND(26) TF_RND(6)   x0 += ks2; x1 += k0  + 5u;
    #undef TF_RND
    *o0 = x0; *o1 = x1;
}

__device__ __forceinline__ void step_key(int step, uint32_t* k0, uint32_t* k1) {
#if RNG_SCHEME == 0
    uint32_t o0, o1;
    int idx0 = 2 * step, idx1 = 2 * step + 1;
    uint32_t blk0 = (idx0 < 32) ? (uint32_t)idx0 : (uint32_t)(idx0 - 32);
    threefry2x32(0u, 42u, blk0, blk0 + 32u, &o0, &o1);
    *k0 = (idx0 < 32) ? o0 : o1;
    uint32_t blk1 = (idx1 < 32) ? (uint32_t)idx1 : (uint32_t)(idx1 - 32);
    threefry2x32(0u, 42u, blk1, blk1 + 32u, &o0, &o1);
    *k1 = (idx1 < 32) ? o0 : o1;
#else
    threefry2x32(0u, 42u, 0u, (uint32_t)step, k0, k1);   // foldlike split
#endif
}

__device__ __forceinline__ void draw_bits(uint32_t k0, uint32_t k1, int lane,
                                          uint32_t* ba, uint32_t* bb) {
#if RNG_SCHEME == 0
    uint32_t r0, r1;
    threefry2x32(k0, k1, (uint32_t)lane, (uint32_t)(lane + 32), &r0, &r1);
    *ba = r0; *bb = r1;
#elif RNG_SCHEME == 1
    uint32_t r0, r1;
    threefry2x32(k0, k1, 0u, (uint32_t)lane,        &r0, &r1); *ba = r0 ^ r1;
    threefry2x32(k0, k1, 0u, (uint32_t)(lane + 32), &r0, &r1); *bb = r0 ^ r1;
#elif RNG_SCHEME == 2
    uint32_t r0, r1;
    threefry2x32(k0, k1, 0u, (uint32_t)lane,        &r0, &r1); *ba = r1;
    threefry2x32(k0, k1, 0u, (uint32_t)(lane + 32), &r0, &r1); *bb = r1;
#else
    uint32_t r0, r1;
    threefry2x32(k0, k1, 0u, (uint32_t)lane,        &r0, &r1); *ba = r0;
    threefry2x32(k0, k1, 0u, (uint32_t)(lane + 32), &r0, &r1); *bb = r0;
#endif
}

// ---------------------------------------------------------------------------
// Layer 1 + fused head. Block = 1 hidden unit; 4 warps split K.
// PRE-SYNC: W_hh1 dots + stage ALL 4 W_ih1 gate slices to smem (16 KB) + L2
// prefetch of head_w. POST-SYNC: input dots from smem, pointwise, last-block
// head (4 warps x 16 rows, L2-hot) + sampling.
// ---------------------------------------------------------------------------
__global__ void __launch_bounds__(L_THREADS, L_MINBLK) lstm_layer1_head_kernel(
    const float* __restrict__ hw,   // [NACT, HDIM] head weights for this step
    const float* __restrict__ hb,   // [NACT]
    float* __restrict__ out, int step, int parity, int write_logp)
{
    __shared__ uint4 s_wi[4][256];                 // 16 KB: [gate][k]
    __shared__ float s_part[4][4];                 // [gate][warp]
    __shared__ float s_logits[NACT];
    __shared__ bool  s_is_last;

    const float* h_in  = g_h[1][parity];
    float*       h_out = g_h[1][parity ^ 1];
    float*       cst   = g_c[1];

    int w    = blockIdx.x;
    int wp   = threadIdx.x >> 5;
    int lane = threadIdx.x & 31;
    int k0   = wp * 64 + lane;

    // L2-prefetch this block's 2 x 128B slice of head_w (512 KB over 2048 blocks)
    if (threadIdx.x < 2) {
        const char* p = (const char*)hw
                      + ((size_t)blockIdx.x * 2 + threadIdx.x) * 128;
        asm volatile("prefetch.global.L2 [%0];" :: "l"(p));
    }

    const float4* h4 = (const float4*)h_in;
    float4 ha0 = h4[2 * k0],        hb0 = h4[2 * k0 + 1];
    float4 ha1 = h4[2 * (k0 + 32)], hb1 = h4[2 * (k0 + 32) + 1];

    float a[4];
    #pragma unroll
    for (int g = 0; g < 4; g++) a[g] = 0.f;

    // PRE-SYNC: recurrent dots + W_ih1 staging (independent of t-state)
    #pragma unroll
    for (int g = 0; g < 4; g++) {
        const uint4* wh = (const uint4*)(g_whh_b[1] + (size_t)(w + g * HDIM) * HDIM);
        const uint4* wi = (const uint4*)(g_wih1_b  + (size_t)(w + g * HDIM) * HDIM);
        s_wi[g][k0]      = __ldcs(&wi[k0]);
        s_wi[g][k0 + 32] = __ldcs(&wi[k0 + 32]);
        a[g] += dot8(__ldcs(&wh[k0]),      ha0, hb0);
        a[g] += dot8(__ldcs(&wh[k0 + 32]), ha1, hb1);
    }

    pdl_wait();       // layer0(t) writes to g_h[0][parity^1] now visible
    pdl_trigger();    // release layer0(t+1)

    {   // POST-SYNC: input half from smem (same-thread addresses, no sync needed)
        const float4* x4 = (const float4*)g_h[0][parity ^ 1];
        float4 xa0 = x4[2 * k0],        xb0 = x4[2 * k0 + 1];
        float4 xa1 = x4[2 * (k0 + 32)], xb1 = x4[2 * (k0 + 32) + 1];
        #pragma unroll
        for (int g = 0; g < 4; g++) {
            a[g] += dot8(s_wi[g][k0],      xa0, xb0);
            a[g] += dot8(s_wi[g][k0 + 32], xa1, xb1);
        }
    }
    #pragma unroll
    for (int g = 0; g < 4; g++) {
        float v = warp_sum(a[g]);
        if (lane == 0) s_part[g][wp] = v;
    }
    __syncthreads();

    if (threadIdx.x == 0) {
        float g0 = s_part[0][0] + s_part[0][1] + s_part[0][2] + s_part[0][3];
        float g1 = s_part[1][0] + s_part[1][1] + s_part[1][2] + s_part[1][3];
        float g2 = s_part[2][0] + s_part[2][1] + s_part[2][2] + s_part[2][3];
        float g3 = s_part[3][0] + s_part[3][1] + s_part[3][2] + s_part[3][3];
        lstm_pointwise4(g0, g1, g2, g3, g_bias[1], w, cst, h_out);
    }

    // ---- last-block detection ----
    __syncthreads();
    if (threadIdx.x == 0) {
        __threadfence();                               // publish h_out write
        unsigned v = atomicAdd(&g_done_ctr, 1u);
        s_is_last = (v == gridDim.x - 1);
    }
    __syncthreads();
    if (!s_is_last) return;                            // block-uniform branch
    __threadfence();                                   // see all blocks' h_out
    if (threadIdx.x == 0) g_done_ctr = 0u;             // reset for next launch

    // ---- head: 4 warps x 16 rows (16 loads in flight/warp, L2-hot) ----
    const float4* hh4 = (const float4*)h_out;
    {
        int rbase = wp * 16;
        float acc[16];
        #pragma unroll
        for (int r = 0; r < 16; r++) acc[r] = 0.f;
        const float4* wbase = (const float4*)hw + (size_t)rbase * 512;
        #pragma unroll 2
        for (int it = 0; it < 16; it++) {
            int k = lane + it * 32;
            float4 hv = hh4[k];
            #pragma unroll
            for (int r = 0; r < 16; r++) {
                float4 aa = wbase[(size_t)r * 512 + k];
                acc[r] += aa.x*hv.x + aa.y*hv.y + aa.z*hv.z + aa.w*hv.w;
            }
        }
        #pragma unroll
        for (int r = 0; r < 16; r++) {
            float v = warp_sum(acc[r]);
            if (lane == 0) s_logits[rbase + r] = v + hb[rbase + r];
        }
    }
    __syncthreads();

    if (wp == 0) {
        uint32_t k0r, k1r;
        step_key(step, &k0r, &k1r);
        uint32_t bits_a, bits_b;
        draw_bits(k0r, k1r, lane, &bits_a, &bits_b);

        const float TINY = 1.1754943508222875e-38f;
        float ua = __uint_as_float((bits_a >> 9) | 0x3f800000u) - 1.0f;
        float ub = __uint_as_float((bits_b >> 9) | 0x3f800000u) - 1.0f;
        ua = fmaxf(ua * (1.0f - TINY) + TINY, TINY);
        ub = fmaxf(ub * (1.0f - TINY) + TINY, TINY);
        float ga = -logf(-logf(ua));
        float gb = -logf(-logf(ub));

        float l0 = s_logits[lane], l1 = s_logits[lane + 32];
        float v0 = l0 + ga, v1 = l1 + gb;

        float bv; int bi;
        if (v1 > v0) { bv = v1; bi = lane + 32; } else { bv = v0; bi = lane; }
        #pragma unroll
        for (int o = 16; o; o >>= 1) {
            float ov = __shfl_xor_sync(0xffffffffu, bv, o);
            int   oi = __shfl_xor_sync(0xffffffffu, bi, o);
            if (ov > bv || (ov == bv && oi < bi)) { bv = ov; bi = oi; }
        }
        float m = fmaxf(l0, l1);
        #pragma unroll
        for (int o = 16; o; o >>= 1) m = fmaxf(m, __shfl_xor_sync(0xffffffffu, m, o));
        float s = expf(l0 - m) + expf(l1 - m);
        #pragma unroll
        for (int o = 16; o; o >>= 1) s += __shfl_xor_sync(0xffffffffu, s, o);

        if (lane == 0) {
            float logp = s_logits[bi] - (logf(s) + m);
            g_action = bi;
            float tot = g_logp + logp;
            g_logp = tot;
            out[step] = (float)bi;
            if (write_logp && step == NSTEPS - 1) out[NSTEPS] = tot;
        }
    }
}

// ---------------------------------------------------------------------------
// PDL-aware launch helpers
// ---------------------------------------------------------------------------
static void launch_layer0(int parity, int step, int pdl) {
    cudaLaunchConfig_t cfg = {};
    cfg.gridDim  = dim3(L_GRID);
    cfg.blockDim = dim3(L_THREADS);
    cfg.stream   = 0;
    cudaLaunchAttribute attr[1];
    attr[0].id = cudaLaunchAttributeProgrammaticStreamSerialization;
    attr[0].val.programmaticStreamSerializationAllowed = 1;
    cfg.attrs    = attr;
    cfg.numAttrs = pdl ? 1 : 0;
    cudaLaunchKernelEx(&cfg, lstm_layer0_kernel, parity, step);
}

static void launch_layer1(const float* hw, const float* hb, float* out,
                          int step, int parity, int write_logp, int pdl) {
    cudaLaunchConfig_t cfg = {};
    cfg.gridDim  = dim3(L_GRID);
    cfg.blockDim = dim3(L_THREADS);
    cfg.stream   = 0;
    cudaLaunchAttribute attr[1];
    attr[0].id = cudaLaunchAttributeProgrammaticStreamSerialization;
    attr[0].val.programmaticStreamSerializationAllowed = 1;
    cfg.attrs    = attr;
    cfg.numAttrs = pdl ? 1 : 0;
    cudaLaunchKernelEx(&cfg, lstm_layer1_head_kernel,
                       hw, hb, out, step, parity, write_logp);
}

// ---------------------------------------------------------------------------
// kernel_launch: prologue + 32 x (layer0, layer1+head)  = 65 graph nodes
// ---------------------------------------------------------------------------
extern "C" void kernel_launch(void* const* d_in, const int* in_sizes, int n_in,
                              void* d_out, int out_size)
{
    const float* start_token = (const float*)d_in[0];
    const float* action_emb  = (const float*)d_in[1];
    const float* w_ih        = (const float*)d_in[2];  // [2, 4H, H]
    const float* w_hh        = (const float*)d_in[3];  // [2, 4H, H]
    const float* b_ih        = (const float*)d_in[4];  // [2, 4H]
    const float* b_hh        = (const float*)d_in[5];  // [2, 4H]
    const float* head_w      = (const float*)d_in[6];  // [32, 64, H]
    const float* head_b      = (const float*)d_in[7];  // [32, 64]
    float* out = (float*)d_out;
    int write_logp = (out_size >= NSTEPS + 1) ? 1 : 0;

    prologue_kernel<<<CONV_BLOCKS + GX_BLOCKS, 256>>>(
        w_ih, w_hh, b_ih, b_hh, action_emb, start_token);

    for (int t = 0; t < NSTEPS; t++) {
        int p = t & 1;
#if USE_PDL
        launch_layer0(p, t, /*pdl=*/t > 0);
        launch_layer1(head_w + (size_t)t * NACT * HDIM,
                      head_b + (size_t)t * NACT,
                      out, t, p, write_logp, /*pdl=*/1);
#else
        launch_layer0(p, t, 0);
        launch_layer1(head_w + (size_t)t * NACT * HDIM,
                      head_b + (size_t)t * NACT,
                      out, t, p, write_logp, 0);
#endif
    }
}